// round 4
// baseline (speedup 1.0000x reference)
#include <cuda_runtime.h>
#include <math.h>

#define DM 1024
#define TS 2048
#define BB 4
#define NH 16
#define HD 64
#define NEG_BIG (-1e30f)

// Scratch (allocation-free rule: __device__ globals)
__device__ float g_qkv[(size_t)BB * TS * 3 * DM];   // [B*T, 3C]
__device__ float g_attn[(size_t)BB * TS * DM];      // [B*T, C]

// ---------------------------------------------------------------------------
// SGEMM + bias: C[M,N] = A[M,K] @ B[K,N] + bias[N]
// 128x128 block tile, BK=16, 256 threads, 8x8 per-thread microtile.
// ---------------------------------------------------------------------------
__global__ __launch_bounds__(256) void sgemm_bias_kernel(
    const float* __restrict__ A, const float* __restrict__ B,
    const float* __restrict__ bias, float* __restrict__ C,
    int M, int N, int K)
{
    __shared__ __align__(16) float As[16][132];  // transposed A tile, +4 pad
    __shared__ __align__(16) float Bs[16][128];

    const int tid = threadIdx.x;
    const int tx  = tid & 15;
    const int ty  = tid >> 4;
    const int row0 = blockIdx.y * 128;
    const int col0 = blockIdx.x * 128;

    const int ar = tid >> 2;        // 0..63
    const int ac = (tid & 3) * 4;   // 0,4,8,12
    const int br = tid >> 5;        // 0..7
    const int bc = (tid & 31) * 4;  // 0..124

    float acc[8][8];
    #pragma unroll
    for (int i = 0; i < 8; i++)
        #pragma unroll
        for (int j = 0; j < 8; j++) acc[i][j] = 0.f;

    for (int k0 = 0; k0 < K; k0 += 16) {
        #pragma unroll
        for (int rr = 0; rr < 2; rr++) {
            int r = ar + rr * 64;
            float4 a = *(const float4*)(A + (size_t)(row0 + r) * K + k0 + ac);
            As[ac + 0][r] = a.x;
            As[ac + 1][r] = a.y;
            As[ac + 2][r] = a.z;
            As[ac + 3][r] = a.w;
        }
        #pragma unroll
        for (int rr = 0; rr < 2; rr++) {
            int r = br + rr * 8;
            *(float4*)&Bs[r][bc] =
                *(const float4*)(B + (size_t)(k0 + r) * N + col0 + bc);
        }
        __syncthreads();

        #pragma unroll
        for (int kk = 0; kk < 16; kk++) {
            float4 a0 = *(const float4*)&As[kk][ty * 8];
            float4 a1 = *(const float4*)&As[kk][ty * 8 + 4];
            float4 b0 = *(const float4*)&Bs[kk][tx * 8];
            float4 b1 = *(const float4*)&Bs[kk][tx * 8 + 4];
            float av[8] = {a0.x, a0.y, a0.z, a0.w, a1.x, a1.y, a1.z, a1.w};
            float bv[8] = {b0.x, b0.y, b0.z, b0.w, b1.x, b1.y, b1.z, b1.w};
            #pragma unroll
            for (int i = 0; i < 8; i++)
                #pragma unroll
                for (int j = 0; j < 8; j++)
                    acc[i][j] = fmaf(av[i], bv[j], acc[i][j]);
        }
        __syncthreads();
    }

    float4 bi0 = *(const float4*)(bias + col0 + tx * 8);
    float4 bi1 = *(const float4*)(bias + col0 + tx * 8 + 4);
    #pragma unroll
    for (int i = 0; i < 8; i++) {
        int row = row0 + ty * 8 + i;
        float4 o0 = make_float4(acc[i][0] + bi0.x, acc[i][1] + bi0.y,
                                acc[i][2] + bi0.z, acc[i][3] + bi0.w);
        float4 o1 = make_float4(acc[i][4] + bi1.x, acc[i][5] + bi1.y,
                                acc[i][6] + bi1.z, acc[i][7] + bi1.w);
        *(float4*)(C + (size_t)row * N + col0 + tx * 8)     = o0;
        *(float4*)(C + (size_t)row * N + col0 + tx * 8 + 4) = o1;
    }
}

// ---------------------------------------------------------------------------
// Flash attention (causal, fp32). One block = 64 queries of one (b,h).
// 256 threads = 16x16 grid; thread owns 4x4 S-tile and 4(q) x 4(d) O-tile.
// ---------------------------------------------------------------------------
__device__ __forceinline__ float redmax16(float v) {
    v = fmaxf(v, __shfl_xor_sync(0xffffffffu, v, 1));
    v = fmaxf(v, __shfl_xor_sync(0xffffffffu, v, 2));
    v = fmaxf(v, __shfl_xor_sync(0xffffffffu, v, 4));
    v = fmaxf(v, __shfl_xor_sync(0xffffffffu, v, 8));
    return v;
}
__device__ __forceinline__ float redsum16(float v) {
    v += __shfl_xor_sync(0xffffffffu, v, 1);
    v += __shfl_xor_sync(0xffffffffu, v, 2);
    v += __shfl_xor_sync(0xffffffffu, v, 4);
    v += __shfl_xor_sync(0xffffffffu, v, 8);
    return v;
}

#define ATTN_SMEM_FLOATS (64*64 + 64*64 + 64*68 + 64*68)
#define ATTN_SMEM_BYTES  (ATTN_SMEM_FLOATS * 4)

__global__ __launch_bounds__(256) void attn_kernel(
    const float* __restrict__ qkv, float* __restrict__ out)
{
    extern __shared__ __align__(16) float sm[];
    float* Qs = sm;                      // [d][qi]  stride 64 (transposed)
    float* Ks = sm + 4096;               // [d][kj]  stride 64 (transposed)
    float* Vs = sm + 8192;               // [kj][d]  stride 68
    float* Ps = sm + 8192 + 64 * 68;     // [qi][kj] stride 68

    const int tid = threadIdx.x;
    const int tx  = tid & 15;            // kj-group (S) / d-group (O)
    const int ty  = tid >> 4;            // qi-group
    const int qt  = blockIdx.x;
    const int b   = blockIdx.y >> 4;
    const int h   = blockIdx.y & 15;

    const int lr = tid >> 2;             // load row 0..63
    const int lc = tid & 3;              // load col-group 0..3

    const float* qbase = qkv + ((size_t)b * TS + (size_t)qt * 64) * (3 * DM) + h * HD;

    // Load Q tile transposed into Qs[d][qi]
    #pragma unroll
    for (int cc = 0; cc < 4; cc++) {
        int c = (lc + cc * 4) * 4;       // 0..60 step 4
        float4 v = *(const float4*)(qbase + (size_t)lr * (3 * DM) + c);
        Qs[(c + 0) * 64 + lr] = v.x;
        Qs[(c + 1) * 64 + lr] = v.y;
        Qs[(c + 2) * 64 + lr] = v.z;
        Qs[(c + 3) * 64 + lr] = v.w;
    }

    float o[4][4];
    float m_i[4], l_i[4];
    #pragma unroll
    for (int i = 0; i < 4; i++) {
        m_i[i] = NEG_BIG; l_i[i] = 0.f;
        #pragma unroll
        for (int j = 0; j < 4; j++) o[i][j] = 0.f;
    }

    for (int kt = 0; kt <= qt; kt++) {
        __syncthreads();
        const float* kbase = qkv + ((size_t)b * TS + (size_t)kt * 64) * (3 * DM) + DM + h * HD;
        const float* vbase = kbase + DM;
        #pragma unroll
        for (int cc = 0; cc < 4; cc++) {
            int c = (lc + cc * 4) * 4;
            float4 kv = *(const float4*)(kbase + (size_t)lr * (3 * DM) + c);
            Ks[(c + 0) * 64 + lr] = kv.x;
            Ks[(c + 1) * 64 + lr] = kv.y;
            Ks[(c + 2) * 64 + lr] = kv.z;
            Ks[(c + 3) * 64 + lr] = kv.w;
            float4 vv = *(const float4*)(vbase + (size_t)lr * (3 * DM) + c);
            *(float4*)&Vs[lr * 68 + c] = vv;
        }
        __syncthreads();

        // S = Q K^T (4x4 per thread)
        float s[4][4];
        #pragma unroll
        for (int i = 0; i < 4; i++)
            #pragma unroll
            for (int j = 0; j < 4; j++) s[i][j] = 0.f;

        #pragma unroll 16
        for (int kk = 0; kk < 64; kk++) {
            float4 q4 = *(const float4*)&Qs[kk * 64 + ty * 4];
            float4 k4 = *(const float4*)&Ks[kk * 64 + tx * 4];
            float qa[4] = {q4.x, q4.y, q4.z, q4.w};
            float ka[4] = {k4.x, k4.y, k4.z, k4.w};
            #pragma unroll
            for (int i = 0; i < 4; i++)
                #pragma unroll
                for (int j = 0; j < 4; j++)
                    s[i][j] = fmaf(qa[i], ka[j], s[i][j]);
        }

        const float sc = 0.125f;   // 1/sqrt(64)
        const bool diag = (kt == qt);
        #pragma unroll
        for (int i = 0; i < 4; i++) {
            #pragma unroll
            for (int j = 0; j < 4; j++) {
                float v = s[i][j] * sc;
                if (diag && (tx * 4 + j) > (ty * 4 + i)) v = NEG_BIG;
                s[i][j] = v;
            }
        }

        // Online softmax per query row (reduce over 16 tx lanes)
        #pragma unroll
        for (int i = 0; i < 4; i++) {
            float mm = fmaxf(fmaxf(s[i][0], s[i][1]), fmaxf(s[i][2], s[i][3]));
            mm = redmax16(mm);
            float mnew  = fmaxf(m_i[i], mm);
            float alpha = __expf(m_i[i] - mnew);
            m_i[i] = mnew;
            float p0 = __expf(s[i][0] - mnew);
            float p1 = __expf(s[i][1] - mnew);
            float p2 = __expf(s[i][2] - mnew);
            float p3 = __expf(s[i][3] - mnew);
            float sum = redsum16(p0 + p1 + p2 + p3);
            l_i[i] = l_i[i] * alpha + sum;
            o[i][0] *= alpha; o[i][1] *= alpha; o[i][2] *= alpha; o[i][3] *= alpha;
            *(float4*)&Ps[(ty * 4 + i) * 68 + tx * 4] = make_float4(p0, p1, p2, p3);
        }
        __syncthreads();

        // O += P V  (thread owns qi-group ty, d-group tx)
        #pragma unroll
        for (int kk = 0; kk < 64; kk += 4) {
            float4 v0 = *(const float4*)&Vs[(kk + 0) * 68 + tx * 4];
            float4 v1 = *(const float4*)&Vs[(kk + 1) * 68 + tx * 4];
            float4 v2 = *(const float4*)&Vs[(kk + 2) * 68 + tx * 4];
            float4 v3 = *(const float4*)&Vs[(kk + 3) * 68 + tx * 4];
            #pragma unroll
            for (int i = 0; i < 4; i++) {
                float4 p = *(const float4*)&Ps[(ty * 4 + i) * 68 + kk];
                o[i][0] = fmaf(p.x, v0.x, fmaf(p.y, v1.x, fmaf(p.z, v2.x, fmaf(p.w, v3.x, o[i][0]))));
                o[i][1] = fmaf(p.x, v0.y, fmaf(p.y, v1.y, fmaf(p.z, v2.y, fmaf(p.w, v3.y, o[i][1]))));
                o[i][2] = fmaf(p.x, v0.z, fmaf(p.y, v1.z, fmaf(p.z, v2.z, fmaf(p.w, v3.z, o[i][2]))));
                o[i][3] = fmaf(p.x, v0.w, fmaf(p.y, v1.w, fmaf(p.z, v2.w, fmaf(p.w, v3.w, o[i][3]))));
            }
        }
    }

    // Epilogue: normalize and write O[b, qi, h*64 + d]
    #pragma unroll
    for (int i = 0; i < 4; i++) {
        float inv = 1.0f / l_i[i];
        int qi = qt * 64 + ty * 4 + i;
        float4 r = make_float4(o[i][0] * inv, o[i][1] * inv,
                               o[i][2] * inv, o[i][3] * inv);
        *(float4*)(out + ((size_t)b * TS + qi) * DM + h * HD + tx * 4) = r;
    }
}

// ---------------------------------------------------------------------------
extern "C" void kernel_launch(void* const* d_in, const int* in_sizes, int n_in,
                              void* d_out, int out_size)
{
    const float* x     = (const float*)d_in[0];
    const float* w_qkv = (const float*)d_in[1];
    const float* b_qkv = (const float*)d_in[2];
    const float* w_out = (const float*)d_in[3];
    const float* b_out = (const float*)d_in[4];
    float* out = (float*)d_out;

    float* qkv  = nullptr;
    float* attn = nullptr;
    cudaGetSymbolAddress((void**)&qkv,  g_qkv);
    cudaGetSymbolAddress((void**)&attn, g_attn);

    cudaFuncSetAttribute(attn_kernel,
                         cudaFuncAttributeMaxDynamicSharedMemorySize,
                         ATTN_SMEM_BYTES);

    const int M = BB * TS;  // 8192

    // QKV projection: [8192,1024] x [1024,3072]
    sgemm_bias_kernel<<<dim3(3 * DM / 128, M / 128), 256>>>(
        x, w_qkv, b_qkv, qkv, M, 3 * DM, DM);

    // Causal attention: grid (q-tiles, B*H)
    attn_kernel<<<dim3(TS / 64, BB * NH), 256, ATTN_SMEM_BYTES>>>(qkv, attn);

    // Output projection: [8192,1024] x [1024,1024]
    sgemm_bias_kernel<<<dim3(DM / 128, M / 128), 256>>>(
        attn, w_out, b_out, out, M, DM, DM);
}